// round 1
// baseline (speedup 1.0000x reference)
#include <cuda_runtime.h>
#include <math.h>

#define N 512
#define FN 8
#define FE 1
#define E 32
#define D0 14   // 6 + FN
#define NF 8    // frames

// ---------------- device scratch (no allocations allowed) ----------------
__device__ float g_Vv[9];        // Vv[i*3+j]: column j = eigenvector j (ascending eigenvalue)
__device__ float g_center[3];
__device__ float g_h0[NF * N * D0];
__device__ float g_pj[NF * N * E];
__device__ float g_pic[NF * N * E];   // pre_i + b1 folded
__device__ float g_agg[NF * N * E];
__device__ float g_h[NF * N * E];     // h1 then h2
__device__ float g_so[NF * N * 6];

// ---------------- setup: center, covariance, 3x3 eigh (Jacobi, double) ----------------
__global__ void k_setup(const float* __restrict__ x) {
    __shared__ float red[512];
    __shared__ float cen[3];
    __shared__ double Rsh[6];
    int t = threadIdx.x;  // 512 threads
    float xv[3];
    xv[0] = x[t * 3 + 0]; xv[1] = x[t * 3 + 1]; xv[2] = x[t * 3 + 2];
    for (int d = 0; d < 3; d++) {
        red[t] = xv[d]; __syncthreads();
        for (int s = 256; s > 0; s >>= 1) { if (t < s) red[t] += red[t + s]; __syncthreads(); }
        if (t == 0) cen[d] = red[0] * (1.0f / N);
        __syncthreads();
    }
    float xc[3] = {xv[0] - cen[0], xv[1] - cen[1], xv[2] - cen[2]};
    const int pi_[6] = {0, 0, 0, 1, 1, 2};
    const int qi_[6] = {0, 1, 2, 1, 2, 2};
    for (int e6 = 0; e6 < 6; e6++) {
        red[t] = xc[pi_[e6]] * xc[qi_[e6]]; __syncthreads();
        for (int s = 256; s > 0; s >>= 1) { if (t < s) red[t] += red[t + s]; __syncthreads(); }
        if (t == 0) Rsh[e6] = (double)red[0];
        __syncthreads();
    }
    if (t == 0) {
        double a[3][3], V[3][3];
        a[0][0] = Rsh[0]; a[0][1] = a[1][0] = Rsh[1]; a[0][2] = a[2][0] = Rsh[2];
        a[1][1] = Rsh[3]; a[1][2] = a[2][1] = Rsh[4]; a[2][2] = Rsh[5];
        for (int i = 0; i < 3; i++) for (int j = 0; j < 3; j++) V[i][j] = (i == j) ? 1.0 : 0.0;
        for (int sweep = 0; sweep < 40; sweep++) {
            double off = a[0][1] * a[0][1] + a[0][2] * a[0][2] + a[1][2] * a[1][2];
            if (off < 1e-26) break;
            for (int pp = 0; pp < 2; pp++) for (int qq = pp + 1; qq < 3; qq++) {
                double apq = a[pp][qq];
                if (fabs(apq) < 1e-300) continue;
                double theta = (a[qq][qq] - a[pp][pp]) / (2.0 * apq);
                double tt = (theta >= 0.0 ? 1.0 : -1.0) / (fabs(theta) + sqrt(theta * theta + 1.0));
                double c = 1.0 / sqrt(tt * tt + 1.0), sn = tt * c;
                double app = a[pp][pp], aqq = a[qq][qq];
                a[pp][pp] = app - tt * apq; a[qq][qq] = aqq + tt * apq;
                a[pp][qq] = a[qq][pp] = 0.0;
                int rr = 3 - pp - qq;
                double arp = a[rr][pp], arq = a[rr][qq];
                a[rr][pp] = a[pp][rr] = c * arp - sn * arq;
                a[rr][qq] = a[qq][rr] = sn * arp + c * arq;
                for (int r = 0; r < 3; r++) {
                    double vrp = V[r][pp], vrq = V[r][qq];
                    V[r][pp] = c * vrp - sn * vrq;
                    V[r][qq] = sn * vrp + c * vrq;
                }
            }
        }
        double w[3] = {a[0][0], a[1][1], a[2][2]};
        int idx[3] = {0, 1, 2};
        for (int i = 0; i < 2; i++) for (int j = i + 1; j < 3; j++)
            if (w[idx[j]] < w[idx[i]]) { int tmp = idx[i]; idx[i] = idx[j]; idx[j] = tmp; }
        for (int j = 0; j < 3; j++) for (int i = 0; i < 3; i++)
            g_Vv[i * 3 + j] = (float)V[i][idx[j]];
        g_center[0] = cen[0]; g_center[1] = cen[1]; g_center[2] = cen[2];
    }
}

// ---------------- embed: build h0 per (frame, node) + layer-0 pj/pic ----------------
__global__ void k_embed(const float* __restrict__ x, const float* __restrict__ v,
                        const float* __restrict__ nfeat,
                        const float* __restrict__ ew1, const float* __restrict__ eb1) {
    __shared__ float sw[(FE + 2 * D0) * E];  // 29*32
    __shared__ float sb[E];
    int t = threadIdx.x;
    for (int i = t; i < (FE + 2 * D0) * E; i += blockDim.x) sw[i] = ew1[i];
    if (t < E) sb[t] = eb1[t];
    __syncthreads();
    int gid = blockIdx.x * blockDim.x + t;
    if (gid >= NF * N) return;
    int o = gid / N, n = gid % N;
    float xc[3], vl[3];
#pragma unroll
    for (int d = 0; d < 3; d++) { xc[d] = x[n * 3 + d] - g_center[d]; vl[d] = v[n * 3 + d]; }
    float h0[D0];
#pragma unroll
    for (int i = 0; i < 3; i++) {
        float sgn = ((o >> (2 - i)) & 1) ? -1.f : 1.f;
        float p = xc[0] * g_Vv[0 * 3 + i] + xc[1] * g_Vv[1 * 3 + i] + xc[2] * g_Vv[2 * 3 + i];
        float q = vl[0] * g_Vv[0 * 3 + i] + vl[1] * g_Vv[1 * 3 + i] + vl[2] * g_Vv[2 * 3 + i];
        h0[i] = sgn * p; h0[3 + i] = sgn * q;
    }
#pragma unroll
    for (int f = 0; f < FN; f++) h0[6 + f] = nfeat[n * FN + f];
#pragma unroll
    for (int d = 0; d < D0; d++) g_h0[gid * D0 + d] = h0[d];
#pragma unroll
    for (int k = 0; k < E; k++) {
        float pj = 0.f, pic = sb[k];
#pragma unroll
        for (int d = 0; d < D0; d++) {
            pj = fmaf(h0[d], sw[(1 + d) * E + k], pj);
            pic = fmaf(h0[d], sw[(1 + D0 + d) * E + k], pic);
        }
        g_pj[gid * E + k] = pj;
        g_pic[gid * E + k] = pic;
    }
}

// ---------------- pair loop: the hot kernel ----------------
// grid (64, 8 frames), block 256 (8 warps); warp w -> row i, lane k -> channel k.
__global__ void __launch_bounds__(256) k_pair(const float* __restrict__ edge,
                                              const float* __restrict__ ew1,   // row 0 = we[k]
                                              const float* __restrict__ ew2,
                                              const float* __restrict__ eb2) {
    int o = blockIdx.y;
    int warp = threadIdx.x >> 5;
    int k = threadIdx.x & 31;
    int i = blockIdx.x * 8 + warp;
    float we = ew1[k];
    float pic = g_pic[(o * N + i) * E + k];
    float b2 = eb2[k];
    float w2c[32];
#pragma unroll
    for (int l = 0; l < 32; l++) w2c[l] = ew2[l * 32 + k];
    const float* pj = g_pj + o * N * E;
    const float* erow = edge + i * N;
    float acc = 0.f;
    for (int j = 0; j < N; j++) {
        float e = __ldg(erow + j);
        float m1 = fmaxf(fmaf(e, we, pj[j * E + k] + pic), 0.f);
        float s0 = b2, s1 = 0.f, s2 = 0.f, s3 = 0.f;
#pragma unroll
        for (int l = 0; l < 32; l += 4) {
            s0 = fmaf(__shfl_sync(0xffffffffu, m1, l + 0), w2c[l + 0], s0);
            s1 = fmaf(__shfl_sync(0xffffffffu, m1, l + 1), w2c[l + 1], s1);
            s2 = fmaf(__shfl_sync(0xffffffffu, m1, l + 2), w2c[l + 2], s2);
            s3 = fmaf(__shfl_sync(0xffffffffu, m1, l + 3), w2c[l + 3], s3);
        }
        acc += fmaxf((s0 + s1) + (s2 + s3), 0.f);
    }
    g_agg[(o * N + i) * E + k] = acc;
}

// ---------------- node update layer 0 -> h1, and layer-1 pj/pic ----------------
__global__ void k_node0(const float* __restrict__ nw1, const float* __restrict__ nb1,
                        const float* __restrict__ nw2, const float* __restrict__ nb2,
                        const float* __restrict__ e1w1, const float* __restrict__ e1b1) {
    __shared__ float s_nw1[(D0 + E) * E];
    __shared__ float s_nw2[E * E];
    __shared__ float s_e1w1[(FE + 2 * E) * E];
    __shared__ float s_nb1[E], s_nb2[E], s_e1b1[E];
    int t = threadIdx.x;
    for (int i = t; i < (D0 + E) * E; i += blockDim.x) s_nw1[i] = nw1[i];
    for (int i = t; i < E * E; i += blockDim.x) s_nw2[i] = nw2[i];
    for (int i = t; i < (FE + 2 * E) * E; i += blockDim.x) s_e1w1[i] = e1w1[i];
    if (t < E) { s_nb1[t] = nb1[t]; s_nb2[t] = nb2[t]; s_e1b1[t] = e1b1[t]; }
    __syncthreads();
    int gid = blockIdx.x * blockDim.x + t;
    if (gid >= NF * N) return;
    float h0l[D0], agg[E];
#pragma unroll
    for (int d = 0; d < D0; d++) h0l[d] = g_h0[gid * D0 + d];
#pragma unroll
    for (int e = 0; e < E; e++) agg[e] = g_agg[gid * E + e];
    float dn[E];
#pragma unroll
    for (int k = 0; k < E; k++) {
        float s = s_nb1[k];
#pragma unroll
        for (int d = 0; d < D0; d++) s = fmaf(h0l[d], s_nw1[d * E + k], s);
#pragma unroll
        for (int e = 0; e < E; e++) s = fmaf(agg[e], s_nw1[(D0 + e) * E + k], s);
        dn[k] = fmaxf(s, 0.f);
    }
    float h1[E];
#pragma unroll
    for (int k = 0; k < E; k++) {
        float s = s_nb2[k];
#pragma unroll
        for (int l = 0; l < E; l++) s = fmaf(dn[l], s_nw2[l * E + k], s);
        h1[k] = s;
        g_h[gid * E + k] = s;
    }
#pragma unroll
    for (int k = 0; k < E; k++) {
        float pjv = 0.f, picv = s_e1b1[k];
#pragma unroll
        for (int d = 0; d < E; d++) {
            pjv = fmaf(h1[d], s_e1w1[(1 + d) * E + k], pjv);
            picv = fmaf(h1[d], s_e1w1[(1 + E + d) * E + k], picv);
        }
        g_pj[gid * E + k] = pjv;
        g_pic[gid * E + k] = picv;
    }
}

// ---------------- node update layer 1 -> h2, decoder -> so ----------------
__global__ void k_node1(const float* __restrict__ nw1, const float* __restrict__ nb1,
                        const float* __restrict__ nw2, const float* __restrict__ nb2,
                        const float* __restrict__ dw1, const float* __restrict__ db1,
                        const float* __restrict__ dw2, const float* __restrict__ db2) {
    __shared__ float s_nw1[2 * E * E];
    __shared__ float s_nw2[E * E];
    __shared__ float s_dw1[E * E];
    __shared__ float s_dw2[E * 6];
    __shared__ float s_nb1[E], s_nb2[E], s_db1[E], s_db2[6];
    int t = threadIdx.x;
    for (int i = t; i < 2 * E * E; i += blockDim.x) s_nw1[i] = nw1[i];
    for (int i = t; i < E * E; i += blockDim.x) { s_nw2[i] = nw2[i]; s_dw1[i] = dw1[i]; }
    for (int i = t; i < E * 6; i += blockDim.x) s_dw2[i] = dw2[i];
    if (t < E) { s_nb1[t] = nb1[t]; s_nb2[t] = nb2[t]; s_db1[t] = db1[t]; }
    if (t < 6) s_db2[t] = db2[t];
    __syncthreads();
    int gid = blockIdx.x * blockDim.x + t;
    if (gid >= NF * N) return;
    float h1l[E], agg[E];
#pragma unroll
    for (int k = 0; k < E; k++) { h1l[k] = g_h[gid * E + k]; agg[k] = g_agg[gid * E + k]; }
    float dn[E];
#pragma unroll
    for (int k = 0; k < E; k++) {
        float s = s_nb1[k];
#pragma unroll
        for (int d = 0; d < E; d++) s = fmaf(h1l[d], s_nw1[d * E + k], s);
#pragma unroll
        for (int d = 0; d < E; d++) s = fmaf(agg[d], s_nw1[(E + d) * E + k], s);
        dn[k] = fmaxf(s, 0.f);
    }
    float h2r[E];
#pragma unroll
    for (int k = 0; k < E; k++) {
        float s = s_nb2[k];
#pragma unroll
        for (int l = 0; l < E; l++) s = fmaf(dn[l], s_nw2[l * E + k], s);
        g_h[gid * E + k] = s;
        h2r[k] = fmaxf(s, 0.f);
    }
    float sd[E];
#pragma unroll
    for (int k = 0; k < E; k++) {
        float s = s_db1[k];
#pragma unroll
        for (int l = 0; l < E; l++) s = fmaf(h2r[l], s_dw1[l * E + k], s);
        sd[k] = fmaxf(s, 0.f);
    }
#pragma unroll
    for (int c = 0; c < 6; c++) {
        float s = s_db2[c];
#pragma unroll
        for (int l = 0; l < E; l++) s = fmaf(sd[l], s_dw2[l * 6 + c], s);
        g_so[gid * 6 + c] = s;
    }
}

// ---------------- final: h_mean, coef, frame inversion, outputs ----------------
__global__ void k_final(const float* __restrict__ x, const float* __restrict__ v,
                        const float* __restrict__ vw1, const float* __restrict__ vb1,
                        const float* __restrict__ vw2, const float* __restrict__ vb2,
                        float* __restrict__ out) {
    __shared__ float s_w1[E * E], s_b1[E], s_w2[E];
    __shared__ float s_b2;
    __shared__ float s_Vv[9];
    int t = threadIdx.x;
    for (int i = t; i < E * E; i += blockDim.x) s_w1[i] = vw1[i];
    if (t < E) { s_b1[t] = vb1[t]; s_w2[t] = vw2[t]; }
    if (t == 0) s_b2 = vb2[0];
    if (t < 9) s_Vv[t] = g_Vv[t];
    __syncthreads();
    int n = blockIdx.x * blockDim.x + t;
    if (n >= N) return;
    float hm[E];
#pragma unroll
    for (int k = 0; k < E; k++) {
        float s = 0.f;
#pragma unroll
        for (int o = 0; o < NF; o++) s += g_h[(o * N + n) * E + k];
        hm[k] = s * 0.125f;
        out[n * E + k] = hm[k];
    }
    float u[E];
#pragma unroll
    for (int k = 0; k < E; k++) {
        float s = s_b1[k];
#pragma unroll
        for (int l = 0; l < E; l++) s = fmaf(fmaxf(hm[l], 0.f), s_w1[l * E + k], s);
        u[k] = fmaxf(s, 0.f);
    }
    float coef = s_b2;
#pragma unroll
    for (int l = 0; l < E; l++) coef = fmaf(u[l], s_w2[l], coef);
    float Sx[3] = {0.f, 0.f, 0.f}, Sv[3] = {0.f, 0.f, 0.f};
#pragma unroll
    for (int o = 0; o < NF; o++) {
#pragma unroll
        for (int j = 0; j < 3; j++) {
            float sgn = ((o >> (2 - j)) & 1) ? -1.f : 1.f;
            Sx[j] += sgn * g_so[(o * N + n) * 6 + j];
            Sv[j] += sgn * g_so[(o * N + n) * 6 + 3 + j];
        }
    }
#pragma unroll
    for (int i = 0; i < 3; i++) {
        float dx = 0.125f * (s_Vv[i * 3 + 0] * Sx[0] + s_Vv[i * 3 + 1] * Sx[1] + s_Vv[i * 3 + 2] * Sx[2]);
        float dv = 0.125f * (s_Vv[i * 3 + 0] * Sv[0] + s_Vv[i * 3 + 1] * Sv[1] + s_Vv[i * 3 + 2] * Sv[2]);
        float vo = v[n * 3 + i] + dv;
        float xo = fmaf(vo, coef, x[n * 3 + i] + dx);
        out[E * N + N * N + n * 3 + i] = xo;
        out[E * N + N * N + 3 * N + n * 3 + i] = vo;
    }
}

__global__ void k_copy(const float4* __restrict__ src, float4* __restrict__ dst, int n4) {
    int i = blockIdx.x * blockDim.x + threadIdx.x;
    if (i < n4) dst[i] = src[i];
}

extern "C" void kernel_launch(void* const* d_in, const int* in_sizes, int n_in,
                              void* d_out, int out_size) {
    const float* node_feat = (const float*)d_in[0];
    const float* edge = (const float*)d_in[1];
    const float* x = (const float*)d_in[2];
    const float* v = (const float*)d_in[3];
    const float* e0w1 = (const float*)d_in[4];
    const float* e0b1 = (const float*)d_in[5];
    const float* e0w2 = (const float*)d_in[6];
    const float* e0b2 = (const float*)d_in[7];
    const float* n0w1 = (const float*)d_in[8];
    const float* n0b1 = (const float*)d_in[9];
    const float* n0w2 = (const float*)d_in[10];
    const float* n0b2 = (const float*)d_in[11];
    const float* e1w1 = (const float*)d_in[12];
    const float* e1b1 = (const float*)d_in[13];
    const float* e1w2 = (const float*)d_in[14];
    const float* e1b2 = (const float*)d_in[15];
    const float* n1w1 = (const float*)d_in[16];
    const float* n1b1 = (const float*)d_in[17];
    const float* n1w2 = (const float*)d_in[18];
    const float* n1b2 = (const float*)d_in[19];
    const float* dw1 = (const float*)d_in[20];
    const float* db1 = (const float*)d_in[21];
    const float* dw2 = (const float*)d_in[22];
    const float* db2 = (const float*)d_in[23];
    const float* vcw1 = (const float*)d_in[24];
    const float* vcb1 = (const float*)d_in[25];
    const float* vcw2 = (const float*)d_in[26];
    const float* vcb2 = (const float*)d_in[27];
    float* out = (float*)d_out;

    k_setup<<<1, 512>>>(x);
    k_embed<<<(NF * N + 255) / 256, 256>>>(x, v, node_feat, e0w1, e0b1);
    k_pair<<<dim3(N / 8, NF), 256>>>(edge, e0w1, e0w2, e0b2);
    k_node0<<<(NF * N + 255) / 256, 256>>>(n0w1, n0b1, n0w2, n0b2, e1w1, e1b1);
    k_pair<<<dim3(N / 8, NF), 256>>>(edge, e1w1, e1w2, e1b2);
    k_node1<<<(NF * N + 255) / 256, 256>>>(n1w1, n1b1, n1w2, n1b2, dw1, db1, dw2, db2);
    k_final<<<2, 256>>>(x, v, vcw1, vcb1, vcw2, vcb2, out);
    k_copy<<<(N * N / 4 + 255) / 256, 256>>>((const float4*)edge, (float4*)(out + E * N), N * N / 4);
}

// round 2
// speedup vs baseline: 1.1086x; 1.1086x over previous
#include <cuda_runtime.h>
#include <math.h>

#define N 512
#define FN 8
#define FE 1
#define E 32
#define D0 14   // 6 + FN
#define NF 8    // frames
#define MS 132  // m1T row stride (conflict-free padding)

// ---------------- device scratch ----------------
__device__ float g_Vv[9];
__device__ float g_center[3];
__device__ float g_h0[NF * N * D0];
__device__ float g_pj[NF * N * E];
__device__ float g_pic[NF * N * E];
__device__ float g_agg[NF * N * E];
__device__ float g_h[NF * N * E];
__device__ float g_so[NF * N * 6];

// packed fp32x2 FMA (Blackwell; ptxas only emits FFMA2 via this PTX form)
__device__ __forceinline__ float2 fma2(float2 a, float2 b, float2 c) {
    unsigned long long au = *reinterpret_cast<unsigned long long*>(&a);
    unsigned long long bu = *reinterpret_cast<unsigned long long*>(&b);
    unsigned long long cu = *reinterpret_cast<unsigned long long*>(&c);
    unsigned long long du;
    asm("fma.rn.f32x2 %0, %1, %2, %3;" : "=l"(du) : "l"(au), "l"(bu), "l"(cu));
    return *reinterpret_cast<float2*>(&du);
}

// ---------------- setup: center, covariance, 3x3 eigh ----------------
__global__ void k_setup(const float* __restrict__ x) {
    __shared__ float red[512];
    __shared__ float cen[3];
    __shared__ double Rsh[6];
    int t = threadIdx.x;
    float xv[3];
    xv[0] = x[t * 3 + 0]; xv[1] = x[t * 3 + 1]; xv[2] = x[t * 3 + 2];
    for (int d = 0; d < 3; d++) {
        red[t] = xv[d]; __syncthreads();
        for (int s = 256; s > 0; s >>= 1) { if (t < s) red[t] += red[t + s]; __syncthreads(); }
        if (t == 0) cen[d] = red[0] * (1.0f / N);
        __syncthreads();
    }
    float xc[3] = {xv[0] - cen[0], xv[1] - cen[1], xv[2] - cen[2]};
    const int pi_[6] = {0, 0, 0, 1, 1, 2};
    const int qi_[6] = {0, 1, 2, 1, 2, 2};
    for (int e6 = 0; e6 < 6; e6++) {
        red[t] = xc[pi_[e6]] * xc[qi_[e6]]; __syncthreads();
        for (int s = 256; s > 0; s >>= 1) { if (t < s) red[t] += red[t + s]; __syncthreads(); }
        if (t == 0) Rsh[e6] = (double)red[0];
        __syncthreads();
    }
    if (t == 0) {
        double a[3][3], V[3][3];
        a[0][0] = Rsh[0]; a[0][1] = a[1][0] = Rsh[1]; a[0][2] = a[2][0] = Rsh[2];
        a[1][1] = Rsh[3]; a[1][2] = a[2][1] = Rsh[4]; a[2][2] = Rsh[5];
        for (int i = 0; i < 3; i++) for (int j = 0; j < 3; j++) V[i][j] = (i == j) ? 1.0 : 0.0;
        for (int sweep = 0; sweep < 40; sweep++) {
            double off = a[0][1] * a[0][1] + a[0][2] * a[0][2] + a[1][2] * a[1][2];
            if (off < 1e-26) break;
            for (int pp = 0; pp < 2; pp++) for (int qq = pp + 1; qq < 3; qq++) {
                double apq = a[pp][qq];
                if (fabs(apq) < 1e-300) continue;
                double theta = (a[qq][qq] - a[pp][pp]) / (2.0 * apq);
                double tt = (theta >= 0.0 ? 1.0 : -1.0) / (fabs(theta) + sqrt(theta * theta + 1.0));
                double c = 1.0 / sqrt(tt * tt + 1.0), sn = tt * c;
                double app = a[pp][pp], aqq = a[qq][qq];
                a[pp][pp] = app - tt * apq; a[qq][qq] = aqq + tt * apq;
                a[pp][qq] = a[qq][pp] = 0.0;
                int rr = 3 - pp - qq;
                double arp = a[rr][pp], arq = a[rr][qq];
                a[rr][pp] = a[pp][rr] = c * arp - sn * arq;
                a[rr][qq] = a[qq][rr] = sn * arp + c * arq;
                for (int r = 0; r < 3; r++) {
                    double vrp = V[r][pp], vrq = V[r][qq];
                    V[r][pp] = c * vrp - sn * vrq;
                    V[r][qq] = sn * vrp + c * vrq;
                }
            }
        }
        double w[3] = {a[0][0], a[1][1], a[2][2]};
        int idx[3] = {0, 1, 2};
        for (int i = 0; i < 2; i++) for (int j = i + 1; j < 3; j++)
            if (w[idx[j]] < w[idx[i]]) { int tmp = idx[i]; idx[i] = idx[j]; idx[j] = tmp; }
        for (int j = 0; j < 3; j++) for (int i = 0; i < 3; i++)
            g_Vv[i * 3 + j] = (float)V[i][idx[j]];
        g_center[0] = cen[0]; g_center[1] = cen[1]; g_center[2] = cen[2];
    }
}

// ---------------- embed: warp per (frame,node) ----------------
__global__ void __launch_bounds__(256) k_embed(const float* __restrict__ x, const float* __restrict__ v,
                                               const float* __restrict__ nfeat,
                                               const float* __restrict__ ew1, const float* __restrict__ eb1) {
    __shared__ float s_wj[D0 * E], s_wi[D0 * E], s_b1[E];
    __shared__ float s_h0[8][16];
    int t = threadIdx.x;
    for (int idx = t; idx < D0 * E; idx += 256) {
        s_wj[idx] = ew1[E + idx];
        s_wi[idx] = ew1[E + D0 * E + idx];
    }
    if (t < E) s_b1[t] = eb1[t];
    __syncthreads();
    int w = t >> 5, k = t & 31;
    int gid = blockIdx.x * 8 + w;
    int o = gid / N, n = gid % N;
    // cooperative h0 build
    if (k < 6) {
        int i = (k < 3) ? k : (k - 3);
        float sgn = ((o >> (2 - i)) & 1) ? -1.f : 1.f;
        float s;
        if (k < 3) {
            s = (x[n * 3 + 0] - g_center[0]) * g_Vv[0 * 3 + i]
              + (x[n * 3 + 1] - g_center[1]) * g_Vv[1 * 3 + i]
              + (x[n * 3 + 2] - g_center[2]) * g_Vv[2 * 3 + i];
        } else {
            s = v[n * 3 + 0] * g_Vv[0 * 3 + i] + v[n * 3 + 1] * g_Vv[1 * 3 + i] + v[n * 3 + 2] * g_Vv[2 * 3 + i];
        }
        s_h0[w][k] = sgn * s;
    } else if (k < D0) {
        s_h0[w][k] = nfeat[n * FN + (k - 6)];
    }
    __syncwarp();
    if (k < D0) g_h0[gid * D0 + k] = s_h0[w][k];
    float pj = 0.f, pic = s_b1[k];
#pragma unroll
    for (int d = 0; d < D0; d++) {
        float h = s_h0[w][d];
        pj = fmaf(h, s_wj[d * E + k], pj);
        pic = fmaf(h, s_wi[d * E + k], pic);
    }
    g_pj[gid * E + k] = pj;
    g_pic[gid * E + k] = pic;
}

// ---------------- pair loop: smem-tiled f32x2 GEMM, no shuffles ----------------
// grid (512 i, 8 frames), block 256. CTA = one (o,i).
__global__ void __launch_bounds__(256) k_pair(const float* __restrict__ edge,
                                              const float* __restrict__ ew1,
                                              const float* __restrict__ ew2,
                                              const float* __restrict__ eb2) {
    __shared__ __align__(16) float m1T[E * MS];     // [l][j] transposed tile
    __shared__ __align__(8) float2 w2dup[E * E];    // (w,w) pairs
    __shared__ __align__(16) float spic[E], swe[E];
    __shared__ float sred[32 * 33];
    int o = blockIdx.y, i = blockIdx.x;
    int t = threadIdx.x;
    for (int idx = t; idx < E * E; idx += 256) {
        float w = ew2[idx];
        w2dup[idx] = make_float2(w, w);
    }
    if (t < E) { swe[t] = ew1[t]; spic[t] = g_pic[(o * N + i) * E + t]; }
    __syncthreads();

    int j = t & 127, l0 = (t >> 7) << 4;   // builder role
    int kg = t & 7, jg = t >> 3;           // consumer role
    int k0 = kg * 4, j0 = jg * 4;
    float b2v[4];
#pragma unroll
    for (int q = 0; q < 4; q++) b2v[q] = __ldg(eb2 + k0 + q);
    float sumk[4] = {0.f, 0.f, 0.f, 0.f};
    const float4* spic4 = (const float4*)spic;
    const float4* swe4 = (const float4*)swe;

    for (int jt = 0; jt < 4; jt++) {
        // phase A: build m1 tile (relu(e*we + pj + pic)), store transposed
        float e = __ldg(edge + i * N + jt * 128 + j);
        const float4* pjv = (const float4*)(g_pj + (size_t)(o * N + jt * 128 + j) * E + l0);
#pragma unroll
        for (int q = 0; q < 4; q++) {
            float4 p = pjv[q];
            float4 pc = spic4[(l0 >> 2) + q];
            float4 wv = swe4[(l0 >> 2) + q];
            int lb = l0 + 4 * q;
            m1T[(lb + 0) * MS + j] = fmaxf(fmaf(e, wv.x, p.x + pc.x), 0.f);
            m1T[(lb + 1) * MS + j] = fmaxf(fmaf(e, wv.y, p.y + pc.y), 0.f);
            m1T[(lb + 2) * MS + j] = fmaxf(fmaf(e, wv.z, p.z + pc.z), 0.f);
            m1T[(lb + 3) * MS + j] = fmaxf(fmaf(e, wv.w, p.w + pc.w), 0.f);
        }
        __syncthreads();
        // phase B: 4j x 4k register block, f32x2 packed along j
        float2 acc[2][4];
#pragma unroll
        for (int q = 0; q < 4; q++) {
            acc[0][q] = make_float2(b2v[q], b2v[q]);
            acc[1][q] = acc[0][q];
        }
#pragma unroll
        for (int l = 0; l < E; l++) {
            float2 a0 = *(const float2*)(m1T + l * MS + j0);
            float2 a1 = *(const float2*)(m1T + l * MS + j0 + 2);
#pragma unroll
            for (int q = 0; q < 4; q++) {
                float2 wq = w2dup[l * E + k0 + q];
                acc[0][q] = fma2(a0, wq, acc[0][q]);
                acc[1][q] = fma2(a1, wq, acc[1][q]);
            }
        }
#pragma unroll
        for (int q = 0; q < 4; q++) {
            sumk[q] += fmaxf(acc[0][q].x, 0.f) + fmaxf(acc[0][q].y, 0.f)
                     + fmaxf(acc[1][q].x, 0.f) + fmaxf(acc[1][q].y, 0.f);
        }
        __syncthreads();
    }
#pragma unroll
    for (int q = 0; q < 4; q++) sred[jg * 33 + k0 + q] = sumk[q];
    __syncthreads();
    if (t < 32) {
        float s = 0.f;
#pragma unroll
        for (int g = 0; g < 32; g++) s += sred[g * 33 + t];
        g_agg[(o * N + i) * E + t] = s;
    }
}

// ---------------- node update layer 0: warp per gid ----------------
__global__ void __launch_bounds__(256) k_node0(const float* __restrict__ nw1, const float* __restrict__ nb1,
                                               const float* __restrict__ nw2, const float* __restrict__ nb2,
                                               const float* __restrict__ e1w1, const float* __restrict__ e1b1) {
    __shared__ float s_nw1[(D0 + E) * E];
    __shared__ float s_nw2[E * E];
    __shared__ float s_ewj[E * E], s_ewi[E * E];
    __shared__ float s_nb1[E], s_nb2[E], s_eb1[E];
    __shared__ float s_a[8][16], s_b[8][32], s_c[8][32];
    int t = threadIdx.x;
    for (int idx = t; idx < (D0 + E) * E; idx += 256) s_nw1[idx] = nw1[idx];
    for (int idx = t; idx < E * E; idx += 256) {
        s_nw2[idx] = nw2[idx];
        s_ewj[idx] = e1w1[E + idx];
        s_ewi[idx] = e1w1[E + E * E + idx];
    }
    if (t < E) { s_nb1[t] = nb1[t]; s_nb2[t] = nb2[t]; s_eb1[t] = e1b1[t]; }
    __syncthreads();
    int w = t >> 5, k = t & 31;
    int gid = blockIdx.x * 8 + w;
    if (k < D0) s_a[w][k] = g_h0[gid * D0 + k];
    s_b[w][k] = g_agg[gid * E + k];
    __syncwarp();
    float dn = s_nb1[k];
#pragma unroll
    for (int d = 0; d < D0; d++) dn = fmaf(s_a[w][d], s_nw1[d * E + k], dn);
#pragma unroll
    for (int d = 0; d < E; d++) dn = fmaf(s_b[w][d], s_nw1[(D0 + d) * E + k], dn);
    dn = fmaxf(dn, 0.f);
    s_c[w][k] = dn;
    __syncwarp();
    float h1 = s_nb2[k];
#pragma unroll
    for (int l = 0; l < E; l++) h1 = fmaf(s_c[w][l], s_nw2[l * E + k], h1);
    g_h[gid * E + k] = h1;
    __syncwarp();
    s_c[w][k] = h1;
    __syncwarp();
    float pj = 0.f, pic = s_eb1[k];
#pragma unroll
    for (int d = 0; d < E; d++) {
        float h = s_c[w][d];
        pj = fmaf(h, s_ewj[d * E + k], pj);
        pic = fmaf(h, s_ewi[d * E + k], pic);
    }
    g_pj[gid * E + k] = pj;
    g_pic[gid * E + k] = pic;
}

// ---------------- node update layer 1 + decoder: warp per gid ----------------
__global__ void __launch_bounds__(256) k_node1(const float* __restrict__ nw1, const float* __restrict__ nb1,
                                               const float* __restrict__ nw2, const float* __restrict__ nb2,
                                               const float* __restrict__ dw1, const float* __restrict__ db1,
                                               const float* __restrict__ dw2, const float* __restrict__ db2) {
    __shared__ float s_nw1[2 * E * E];
    __shared__ float s_nw2[E * E];
    __shared__ float s_dw1[E * E];
    __shared__ float s_dw2[E * 6];
    __shared__ float s_nb1[E], s_nb2[E], s_db1[E], s_db2[6];
    __shared__ float s_a[8][32], s_b[8][32], s_c[8][32];
    int t = threadIdx.x;
    for (int idx = t; idx < 2 * E * E; idx += 256) s_nw1[idx] = nw1[idx];
    for (int idx = t; idx < E * E; idx += 256) { s_nw2[idx] = nw2[idx]; s_dw1[idx] = dw1[idx]; }
    for (int idx = t; idx < E * 6; idx += 256) s_dw2[idx] = dw2[idx];
    if (t < E) { s_nb1[t] = nb1[t]; s_nb2[t] = nb2[t]; s_db1[t] = db1[t]; }
    if (t < 6) s_db2[t] = db2[t];
    __syncthreads();
    int w = t >> 5, k = t & 31;
    int gid = blockIdx.x * 8 + w;
    s_a[w][k] = g_h[gid * E + k];
    s_b[w][k] = g_agg[gid * E + k];
    __syncwarp();
    float dn = s_nb1[k];
#pragma unroll
    for (int d = 0; d < E; d++) dn = fmaf(s_a[w][d], s_nw1[d * E + k], dn);
#pragma unroll
    for (int d = 0; d < E; d++) dn = fmaf(s_b[w][d], s_nw1[(E + d) * E + k], dn);
    dn = fmaxf(dn, 0.f);
    s_c[w][k] = dn;
    __syncwarp();
    float h2 = s_nb2[k];
#pragma unroll
    for (int l = 0; l < E; l++) h2 = fmaf(s_c[w][l], s_nw2[l * E + k], h2);
    g_h[gid * E + k] = h2;
    __syncwarp();
    s_a[w][k] = fmaxf(h2, 0.f);
    __syncwarp();
    float sd = s_db1[k];
#pragma unroll
    for (int l = 0; l < E; l++) sd = fmaf(s_a[w][l], s_dw1[l * E + k], sd);
    sd = fmaxf(sd, 0.f);
    s_b[w][k] = sd;
    __syncwarp();
    if (k < 6) {
        float s = s_db2[k];
#pragma unroll
        for (int l = 0; l < E; l++) s = fmaf(s_b[w][l], s_dw2[l * 6 + k], s);
        g_so[gid * 6 + k] = s;
    }
}

// ---------------- final: h_mean, coef, frame inversion, outputs ----------------
__global__ void k_final(const float* __restrict__ x, const float* __restrict__ v,
                        const float* __restrict__ vw1, const float* __restrict__ vb1,
                        const float* __restrict__ vw2, const float* __restrict__ vb2,
                        float* __restrict__ out) {
    __shared__ float s_w1[E * E], s_b1[E], s_w2[E];
    __shared__ float s_b2;
    __shared__ float s_Vv[9];
    int t = threadIdx.x;
    for (int i = t; i < E * E; i += blockDim.x) s_w1[i] = vw1[i];
    if (t < E) { s_b1[t] = vb1[t]; s_w2[t] = vw2[t]; }
    if (t == 0) s_b2 = vb2[0];
    if (t < 9) s_Vv[t] = g_Vv[t];
    __syncthreads();
    int n = blockIdx.x * blockDim.x + t;
    if (n >= N) return;
    float hm[E];
#pragma unroll
    for (int k = 0; k < E; k++) {
        float s = 0.f;
#pragma unroll
        for (int o = 0; o < NF; o++) s += g_h[(o * N + n) * E + k];
        hm[k] = s * 0.125f;
        out[n * E + k] = hm[k];
    }
    float u[E];
#pragma unroll
    for (int k = 0; k < E; k++) {
        float s = s_b1[k];
#pragma unroll
        for (int l = 0; l < E; l++) s = fmaf(fmaxf(hm[l], 0.f), s_w1[l * E + k], s);
        u[k] = fmaxf(s, 0.f);
    }
    float coef = s_b2;
#pragma unroll
    for (int l = 0; l < E; l++) coef = fmaf(u[l], s_w2[l], coef);
    float Sx[3] = {0.f, 0.f, 0.f}, Sv[3] = {0.f, 0.f, 0.f};
#pragma unroll
    for (int o = 0; o < NF; o++) {
#pragma unroll
        for (int jj = 0; jj < 3; jj++) {
            float sgn = ((o >> (2 - jj)) & 1) ? -1.f : 1.f;
            Sx[jj] += sgn * g_so[(o * N + n) * 6 + jj];
            Sv[jj] += sgn * g_so[(o * N + n) * 6 + 3 + jj];
        }
    }
#pragma unroll
    for (int i = 0; i < 3; i++) {
        float dx = 0.125f * (s_Vv[i * 3 + 0] * Sx[0] + s_Vv[i * 3 + 1] * Sx[1] + s_Vv[i * 3 + 2] * Sx[2]);
        float dv = 0.125f * (s_Vv[i * 3 + 0] * Sv[0] + s_Vv[i * 3 + 1] * Sv[1] + s_Vv[i * 3 + 2] * Sv[2]);
        float vo = v[n * 3 + i] + dv;
        float xo = fmaf(vo, coef, x[n * 3 + i] + dx);
        out[E * N + N * N + n * 3 + i] = xo;
        out[E * N + N * N + 3 * N + n * 3 + i] = vo;
    }
}

__global__ void k_copy(const float4* __restrict__ src, float4* __restrict__ dst, int n4) {
    int i = blockIdx.x * blockDim.x + threadIdx.x;
    if (i < n4) dst[i] = src[i];
}

extern "C" void kernel_launch(void* const* d_in, const int* in_sizes, int n_in,
                              void* d_out, int out_size) {
    const float* node_feat = (const float*)d_in[0];
    const float* edge = (const float*)d_in[1];
    const float* x = (const float*)d_in[2];
    const float* v = (const float*)d_in[3];
    const float* e0w1 = (const float*)d_in[4];
    const float* e0b1 = (const float*)d_in[5];
    const float* e0w2 = (const float*)d_in[6];
    const float* e0b2 = (const float*)d_in[7];
    const float* n0w1 = (const float*)d_in[8];
    const float* n0b1 = (const float*)d_in[9];
    const float* n0w2 = (const float*)d_in[10];
    const float* n0b2 = (const float*)d_in[11];
    const float* e1w1 = (const float*)d_in[12];
    const float* e1b1 = (const float*)d_in[13];
    const float* e1w2 = (const float*)d_in[14];
    const float* e1b2 = (const float*)d_in[15];
    const float* n1w1 = (const float*)d_in[16];
    const float* n1b1 = (const float*)d_in[17];
    const float* n1w2 = (const float*)d_in[18];
    const float* n1b2 = (const float*)d_in[19];
    const float* dw1 = (const float*)d_in[20];
    const float* db1 = (const float*)d_in[21];
    const float* dw2 = (const float*)d_in[22];
    const float* db2 = (const float*)d_in[23];
    const float* vcw1 = (const float*)d_in[24];
    const float* vcb1 = (const float*)d_in[25];
    const float* vcw2 = (const float*)d_in[26];
    const float* vcb2 = (const float*)d_in[27];
    float* out = (float*)d_out;

    k_setup<<<1, 512>>>(x);
    k_embed<<<NF * N / 8, 256>>>(x, v, node_feat, e0w1, e0b1);
    k_pair<<<dim3(N, NF), 256>>>(edge, e0w1, e0w2, e0b2);
    k_node0<<<NF * N / 8, 256>>>(n0w1, n0b1, n0w2, n0b2, e1w1, e1b1);
    k_pair<<<dim3(N, NF), 256>>>(edge, e1w1, e1w2, e1b2);
    k_node1<<<NF * N / 8, 256>>>(n1w1, n1b1, n1w2, n1b2, dw1, db1, dw2, db2);
    k_final<<<2, 256>>>(x, v, vcw1, vcb1, vcw2, vcb2, out);
    k_copy<<<(N * N / 4 + 255) / 256, 256>>>((const float4*)edge, (float4*)(out + E * N), N * N / 4);
}